// round 1
// baseline (speedup 1.0000x reference)
#include <cuda_runtime.h>
#include <math.h>
#include <stdint.h>

#define BB 64
#define UU 512
#define EMBD 256
#define NS 32
#define NW 50
#define VV 50000
#define EXT 50100

// d_out layout: [dec 64*512][gen 64*50100][copy 64*50100][p_gen 64]
#define GEN_OFF   ((size_t)BB*UU)
#define COPY_OFF  (GEN_OFF + (size_t)BB*EXT)
#define PGEN_OFF  (COPY_OFF + (size_t)BB*EXT)

// ------------- scratch (no allocations allowed) -------------
__device__ float g_xm[BB*1536];
__device__ float g_hm[BB*1536];
__device__ float g_q[BB*UU];
__device__ float g_qw[BB*UU];
__device__ float g_alpha[BB*NS];
__device__ float g_xcat[BB*1024];   // [context | dec]
__device__ float g_ht[BB*256];
__device__ float g_rowsum[BB];

// ------------- init: zero copy region, gen padding, rowsums -------------
__global__ void k_init(float* __restrict__ out) {
    size_t i = (size_t)blockIdx.x * blockDim.x + threadIdx.x;
    size_t total = (size_t)BB * EXT;
    size_t stride = (size_t)gridDim.x * blockDim.x;
    for (size_t t = i; t < total; t += stride) {
        out[COPY_OFF + t] = 0.0f;
        int v = (int)(t % EXT);
        if (v >= VV) out[GEN_OFF + t] = 0.0f;
    }
    if (i < BB) g_rowsum[i] = 0.0f;
}

// ------------- generic small GEMM: C[64,N] = A[64,K] @ W[K,N] (+bias, opt tanh) ----
// 256 threads; block computes 64 rows x 32 cols. K,N multiples of 32.
__global__ void k_gemm(const float* __restrict__ A, const float* __restrict__ W,
                       const float* __restrict__ bias, float* __restrict__ C,
                       int K, int N, int act) {
    __shared__ __align__(16) float As[32 * 68];   // [k][b] padded
    __shared__ __align__(16) float Wt[32 * 32];   // [k][c]
    int tid = threadIdx.x;
    int c  = tid & 31;
    int rg = tid >> 5;            // 8 row groups of 8 rows
    int n0 = blockIdx.x * 32;
    int n  = n0 + c;

    float acc[8];
#pragma unroll
    for (int r = 0; r < 8; r++) acc[r] = 0.0f;

    for (int k0 = 0; k0 < K; k0 += 32) {
        for (int i = tid; i < 2048; i += 256) {
            int k = i & 31, b = i >> 5;
            As[k * 68 + b] = A[(size_t)b * K + k0 + k];
        }
        for (int i = tid; i < 1024; i += 256) {
            int kk = i >> 5, c2 = i & 31;
            Wt[kk * 32 + c2] = W[(size_t)(k0 + kk) * N + n0 + c2];
        }
        __syncthreads();
#pragma unroll 8
        for (int kk = 0; kk < 32; kk++) {
            float w = Wt[kk * 32 + c];
            float4 a0 = *(const float4*)&As[kk * 68 + rg * 8];
            float4 a1 = *(const float4*)&As[kk * 68 + rg * 8 + 4];
            acc[0] += a0.x * w; acc[1] += a0.y * w;
            acc[2] += a0.z * w; acc[3] += a0.w * w;
            acc[4] += a1.x * w; acc[5] += a1.y * w;
            acc[6] += a1.z * w; acc[7] += a1.w * w;
        }
        __syncthreads();
    }
    float bv = bias ? bias[n] : 0.0f;
#pragma unroll
    for (int r = 0; r < 8; r++) {
        float v = acc[r] + bv;
        if (act == 1) v = tanhf(v);
        C[(size_t)(rg * 8 + r) * N + n] = v;
    }
}

// ------------- GRU gate combine -> dec_output -------------
__global__ void k_comb(const float* __restrict__ hid, float* __restrict__ out) {
    int idx = blockIdx.x * 256 + threadIdx.x;   // 64*512 threads
    int b = idx >> 9, u = idx & 511;
    float xz = g_xm[b * 1536 + u];
    float xr = g_xm[b * 1536 + 512 + u];
    float xh = g_xm[b * 1536 + 1024 + u];
    float hz = g_hm[b * 1536 + u];
    float hr = g_hm[b * 1536 + 512 + u];
    float hh = g_hm[b * 1536 + 1024 + u];
    float z = 1.0f / (1.0f + __expf(-(xz + hz)));
    float r = 1.0f / (1.0f + __expf(-(xr + hr)));
    float hc = tanhf(xh + r * hh);
    float hp = hid[idx];
    float d = z * hp + (1.0f - z) * hc;
    out[idx] = d;
    g_xcat[b * 1024 + 512 + u] = d;
}

// ------------- sentence attention + context + p_gen (block per b) -------------
__global__ void k_att(const float* __restrict__ enc_s, const float* __restrict__ dec,
                      const float* __restrict__ emb, const float* __restrict__ wc,
                      const float* __restrict__ wh, const float* __restrict__ wi,
                      float* __restrict__ out) {
    int b = blockIdx.x;
    __shared__ __align__(16) float qs[512];
    __shared__ float ctx[512];
    __shared__ float sc[32];
    __shared__ float red[8];
    int tid = threadIdx.x, wid = tid >> 5, lane = tid & 31;

    qs[tid] = g_q[b * 512 + tid];
    qs[tid + 256] = g_q[b * 512 + tid + 256];
    __syncthreads();

    const float4* qv4 = (const float4*)qs;
    for (int s = wid; s < NS; s += 8) {
        const float4* e = (const float4*)(enc_s + ((size_t)b * NS + s) * 512);
        float sum = 0.0f;
#pragma unroll
        for (int j = 0; j < 4; j++) {
            float4 ev = e[lane + 32 * j];
            float4 qv = qv4[lane + 32 * j];
            sum += ev.x * qv.x + ev.y * qv.y + ev.z * qv.z + ev.w * qv.w;
        }
#pragma unroll
        for (int o = 16; o; o >>= 1) sum += __shfl_xor_sync(0xffffffffu, sum, o);
        if (lane == 0) sc[s] = sum;
    }
    __syncthreads();
    if (wid == 0) {
        float v = sc[lane];
        float m = v;
#pragma unroll
        for (int o = 16; o; o >>= 1) m = fmaxf(m, __shfl_xor_sync(0xffffffffu, m, o));
        float e = __expf(v - m);
        float Z = e;
#pragma unroll
        for (int o = 16; o; o >>= 1) Z += __shfl_xor_sync(0xffffffffu, Z, o);
        float a = e / Z;
        sc[lane] = a;
        g_alpha[b * NS + lane] = a;
    }
    __syncthreads();
    for (int d = tid; d < 512; d += 256) {
        float s = 0.0f;
#pragma unroll 8
        for (int k = 0; k < NS; k++) s += sc[k] * enc_s[((size_t)b * NS + k) * 512 + d];
        ctx[d] = s;
        g_xcat[b * 1024 + d] = s;
    }
    __syncthreads();
    // p_gen
    float p = ctx[tid] * wc[tid] + ctx[tid + 256] * wc[tid + 256];
    p += dec[b * 512 + tid] * wh[tid] + dec[b * 512 + tid + 256] * wh[tid + 256];
    p += emb[b * 256 + tid] * wi[tid];
#pragma unroll
    for (int o = 16; o; o >>= 1) p += __shfl_xor_sync(0xffffffffu, p, o);
    if (lane == 0) red[wid] = p;
    __syncthreads();
    if (tid == 0) {
        float t = 0.0f;
        for (int w = 0; w < 8; w++) t += red[w];
        out[PGEN_OFF + b] = 1.0f / (1.0f + __expf(-t));
    }
}

// ------------- FC + exp + row-sum partials (8b x 8v register tile) -------------
// grid: ceil(50000/128) blocks of 128 threads, dynamic smem: h[64][260] + wt[32][128]
__global__ void k_fc(const float* __restrict__ fcW, const float* __restrict__ fcb,
                     float* __restrict__ out) {
    extern __shared__ __align__(16) float sm[];
    float* hs = sm;               // [64][260]
    float* wt = sm + 64 * 260;    // [32][128]
    __shared__ float bsum[64];

    int tid = threadIdx.x;
    int v0 = blockIdx.x * 128;
    int vg = tid & 15, bg = tid >> 4;
    int vb = v0 + vg * 8;

    // stage h (transpose-free: row-major [b][k] padded to 260)
    for (int i4 = tid; i4 < 4096; i4 += 128) {
        int e = i4 * 4;
        int b = e >> 8, k = e & 255;
        float4 hv = *(const float4*)(g_ht + e);
        *(float4*)&hs[b * 260 + k] = hv;
    }
    if (tid < 64) bsum[tid] = 0.0f;

    float acc[8][8];
#pragma unroll
    for (int r = 0; r < 8; r++)
#pragma unroll
        for (int cc = 0; cc < 8; cc++) acc[r][cc] = 0.0f;

    for (int kc = 0; kc < 8; kc++) {
        __syncthreads();
        for (int i4 = tid; i4 < 1024; i4 += 128) {
            int e = i4 * 4;
            int kk = e >> 7, vv = e & 127;
            int v = v0 + vv;
            float4 w4 = make_float4(0.f, 0.f, 0.f, 0.f);
            if (v + 3 < VV) {
                w4 = *(const float4*)(fcW + (size_t)(kc * 32 + kk) * VV + v);
            } else {
                if (v     < VV) w4.x = fcW[(size_t)(kc * 32 + kk) * VV + v];
                if (v + 1 < VV) w4.y = fcW[(size_t)(kc * 32 + kk) * VV + v + 1];
                if (v + 2 < VV) w4.z = fcW[(size_t)(kc * 32 + kk) * VV + v + 2];
            }
            *(float4*)&wt[kk * 128 + vv] = w4;
        }
        __syncthreads();
#pragma unroll 4
        for (int kk = 0; kk < 32; kk++) {
            int k = kc * 32 + kk;
            float4 w0 = *(const float4*)&wt[kk * 128 + vg * 8];
            float4 w1 = *(const float4*)&wt[kk * 128 + vg * 8 + 4];
            float w[8] = {w0.x, w0.y, w0.z, w0.w, w1.x, w1.y, w1.z, w1.w};
#pragma unroll
            for (int r = 0; r < 8; r++) {
                float hv = hs[(bg * 8 + r) * 260 + k];
#pragma unroll
                for (int cc = 0; cc < 8; cc++) acc[r][cc] += hv * w[cc];
            }
        }
    }

    // epilogue: exp(logit+bias) -> d_out gen region; partial row sums
    float bias[8];
#pragma unroll
    for (int cc = 0; cc < 8; cc++) bias[cc] = (vb + cc < VV) ? fcb[vb + cc] : 0.0f;

    float sums[8];
#pragma unroll
    for (int r = 0; r < 8; r++) sums[r] = 0.0f;

#pragma unroll
    for (int r = 0; r < 8; r++) {
        int b = bg * 8 + r;
        float ev[8];
#pragma unroll
        for (int cc = 0; cc < 8; cc++) {
            float e = 0.0f;
            if (vb + cc < VV) {
                e = __expf(acc[r][cc] + bias[cc]);
                sums[r] += e;
            }
            ev[cc] = e;
        }
        if (vb + 7 < VV) {
            float* dst = out + GEN_OFF + (size_t)b * EXT + vb;
            *(float4*)dst       = make_float4(ev[0], ev[1], ev[2], ev[3]);
            *(float4*)(dst + 4) = make_float4(ev[4], ev[5], ev[6], ev[7]);
        } else {
#pragma unroll
            for (int cc = 0; cc < 8; cc++)
                if (vb + cc < VV) out[GEN_OFF + (size_t)b * EXT + vb + cc] = ev[cc];
        }
    }
    __syncthreads();
#pragma unroll
    for (int r = 0; r < 8; r++) atomicAdd(&bsum[bg * 8 + r], sums[r]);
    __syncthreads();
    if (tid < 64) atomicAdd(&g_rowsum[tid], bsum[tid]);
}

// ------------- normalize gen distribution -------------
__global__ void k_norm(float* __restrict__ out) {
    size_t i = (size_t)blockIdx.x * blockDim.x + threadIdx.x;
    size_t stride = (size_t)gridDim.x * blockDim.x;
    size_t total = (size_t)BB * EXT;
    for (size_t t = i; t < total; t += stride) {
        int v = (int)(t % EXT);
        if (v < VV) {
            int b = (int)(t / EXT);
            out[GEN_OFF + t] *= (1.0f / g_rowsum[b]);
        }
    }
}

// ------------- word attention + scatter-add copy distribution -------------
__global__ void k_watt(const float* __restrict__ enc_w, const int* __restrict__ num,
                       float* __restrict__ out) {
    int b = blockIdx.x >> 5;
    int s = blockIdx.x & 31;
    __shared__ __align__(16) float qs[512];
    __shared__ float sc[64];
    int tid = threadIdx.x, wid = tid >> 5, lane = tid & 31;

    qs[tid] = g_qw[b * 512 + tid];
    qs[tid + 256] = g_qw[b * 512 + tid + 256];
    __syncthreads();

    const float4* qv4 = (const float4*)qs;
    for (int w = wid; w < NW; w += 8) {
        const float4* e = (const float4*)(enc_w + (((size_t)b * NS + s) * NW + w) * 512);
        float sum = 0.0f;
#pragma unroll
        for (int j = 0; j < 4; j++) {
            float4 ev = e[lane + 32 * j];
            float4 qv = qv4[lane + 32 * j];
            sum += ev.x * qv.x + ev.y * qv.y + ev.z * qv.z + ev.w * qv.w;
        }
#pragma unroll
        for (int o = 16; o; o >>= 1) sum += __shfl_xor_sync(0xffffffffu, sum, o);
        if (lane == 0) sc[w] = sum;
    }
    __syncthreads();
    if (wid == 0) {
        float v0 = (lane < NW) ? sc[lane] : -1e30f;
        float v1 = (lane + 32 < NW) ? sc[lane + 32] : -1e30f;
        float m = fmaxf(v0, v1);
#pragma unroll
        for (int o = 16; o; o >>= 1) m = fmaxf(m, __shfl_xor_sync(0xffffffffu, m, o));
        float e0 = (lane < NW) ? __expf(v0 - m) : 0.0f;
        float e1 = (lane + 32 < NW) ? __expf(v1 - m) : 0.0f;
        float Z = e0 + e1;
#pragma unroll
        for (int o = 16; o; o >>= 1) Z += __shfl_xor_sync(0xffffffffu, Z, o);
        float a = g_alpha[b * NS + s] / Z;
        if (lane < NW) sc[lane] = e0 * a;
        if (lane + 32 < NW) sc[lane + 32] = e1 * a;
    }
    __syncthreads();
    if (tid < NW) {
        int idx = num[b * (NS * NW) + s * NW + tid];
        atomicAdd(out + COPY_OFF + (size_t)b * EXT + idx, sc[tid]);
    }
}

// =================== host ===================
extern "C" void kernel_launch(void* const* d_in, const int* in_sizes, int n_in,
                              void* d_out, int out_size) {
    const float *emb = 0, *hid = 0, *enc_s = 0, *enc_w = 0;
    const float *Wx = 0, *Wh = 0, *gb = 0, *Ws = 0, *Ww = 0;
    const float *fcW = 0, *fcb = 0, *wc = 0, *wh = 0, *wd = 0, *wi = 0;
    const int* num = 0;
    int c262 = 0, c512 = 0;
    for (int i = 0; i < n_in; i++) {
        int sz = in_sizes[i];
        const float* p = (const float*)d_in[i];
        switch (sz) {
            case 16384:    emb = p; break;
            case 32768:    hid = p; break;
            case 1048576:  enc_s = p; break;
            case 52428800: enc_w = p; break;
            case 102400:   num = (const int*)d_in[i]; break;
            case 393216:   Wx = p; break;
            case 786432:   Wh = p; break;
            case 3072:     gb = p; break;
            case 12800000: fcW = p; break;
            case 50000:    fcb = p; break;
            case 256:      wi = p; break;
            case 512:      if (c512 == 0) wc = p; else wh = p; c512++; break;
            case 262144:
                if (c262 == 0) Ws = p; else if (c262 == 1) Ww = p; else wd = p;
                c262++; break;
            default: break; // batch_size scalar
        }
    }
    float* out = (float*)d_out;

    float *xcat_ptr = 0, *ht_ptr = 0;
    cudaGetSymbolAddress((void**)&xcat_ptr, g_xcat);
    cudaGetSymbolAddress((void**)&ht_ptr, g_ht);

    float *xm_ptr = 0, *hm_ptr = 0, *q_ptr = 0, *qw_ptr = 0;
    cudaGetSymbolAddress((void**)&xm_ptr, g_xm);
    cudaGetSymbolAddress((void**)&hm_ptr, g_hm);
    cudaGetSymbolAddress((void**)&q_ptr, g_q);
    cudaGetSymbolAddress((void**)&qw_ptr, g_qw);

    int fc_smem = (64 * 260 + 32 * 128) * 4;
    cudaFuncSetAttribute(k_fc, cudaFuncAttributeMaxDynamicSharedMemorySize, fc_smem);

    k_init<<<2048, 256>>>(out);
    // GRU gate GEMMs: xm = x@Wx + b0 ; hm = h@Wh + b1
    k_gemm<<<48, 256>>>(emb, Wx, gb, xm_ptr, 256, 1536, 0);
    k_gemm<<<48, 256>>>(hid, Wh, gb + 1536, hm_ptr, 512, 1536, 0);
    k_comb<<<128, 256>>>(hid, out);
    // q, qw
    k_gemm<<<16, 256>>>(out, Ws, 0, q_ptr, 512, 512, 0);
    k_gemm<<<16, 256>>>(out, Ww, 0, qw_ptr, 512, 512, 0);
    // sentence attention, context, p_gen
    k_att<<<64, 256>>>(enc_s, out, emb, wc, wh, wi, out);
    // hidden_t = tanh([ctx|dec] @ weight_dec)
    k_gemm<<<8, 256>>>(xcat_ptr, wd, 0, ht_ptr, 1024, 256, 1);
    // vocabulary distribution
    k_fc<<<(VV + 127) / 128, 128, fc_smem>>>(fcW, fcb, out);
    k_norm<<<6144, 256>>>(out);
    // word attention + copy distribution scatter
    k_watt<<<BB * NS, 256>>>(enc_w, num, out);
}

// round 2
// speedup vs baseline: 1.7483x; 1.7483x over previous
#include <cuda_runtime.h>
#include <math.h>
#include <stdint.h>

#define BB 64
#define UU 512
#define EMBD 256
#define NS 32
#define NW 50
#define VV 50000
#define EXT 50100

// d_out layout: [dec 64*512][gen 64*50100][copy 64*50100][p_gen 64]
#define GEN_OFF   ((size_t)BB*UU)
#define COPY_OFF  (GEN_OFF + (size_t)BB*EXT)
#define PGEN_OFF  (COPY_OFF + (size_t)BB*EXT)

// ------------- scratch (no allocations allowed) -------------
__device__ float g_xm[BB*1536];
__device__ float g_hm[BB*1536];
__device__ float g_q[BB*UU];
__device__ float g_qw[BB*UU];
__device__ float g_alpha[BB*NS];
__device__ float g_ht[BB*256];
__device__ float g_rowsum[BB];

// ------------- helpers -------------
__device__ __forceinline__ uint32_t f2tf32(float f) {
    uint32_t u;
    asm("cvt.rna.tf32.f32 %0, %1;" : "=r"(u) : "f"(f));
    return u;
}

__device__ __forceinline__ void mma_tf32(float& c0, float& c1, float& c2, float& c3,
                                         uint32_t a0, uint32_t a1, uint32_t a2, uint32_t a3,
                                         uint32_t b0, uint32_t b1) {
    asm volatile(
        "mma.sync.aligned.m16n8k8.row.col.f32.tf32.tf32.f32 "
        "{%0,%1,%2,%3}, {%4,%5,%6,%7}, {%8,%9}, {%0,%1,%2,%3};\n"
        : "+f"(c0), "+f"(c1), "+f"(c2), "+f"(c3)
        : "r"(a0), "r"(a1), "r"(a2), "r"(a3), "r"(b0), "r"(b1));
}

// ------------- init: zero copy region, gen padding, rowsums -------------
__global__ void k_init(float* __restrict__ out) {
    size_t i = (size_t)blockIdx.x * blockDim.x + threadIdx.x;
    size_t total = (size_t)BB * EXT;
    size_t stride = (size_t)gridDim.x * blockDim.x;
    for (size_t t = i; t < total; t += stride) {
        out[COPY_OFF + t] = 0.0f;
        int v = (int)(t % EXT);
        if (v >= VV) out[GEN_OFF + t] = 0.0f;
    }
    if (i < BB) g_rowsum[i] = 0.0f;
}

// ------------- small GEMM tile device func: C[64,N] tile of 32 cols -------------
__device__ __forceinline__ void gemm_tile(float* As, float* Wt,
                                          const float* __restrict__ A,
                                          const float* __restrict__ W,
                                          const float* __restrict__ bias,
                                          float* __restrict__ C,
                                          int K, int N, int blk, int act) {
    int tid = threadIdx.x;
    int c  = tid & 31;
    int rg = tid >> 5;            // 8 row groups of 8 rows
    int n0 = blk * 32;
    int n  = n0 + c;

    float acc[8];
#pragma unroll
    for (int r = 0; r < 8; r++) acc[r] = 0.0f;

    for (int k0 = 0; k0 < K; k0 += 32) {
        for (int i = tid; i < 2048; i += 256) {
            int k = i & 31, b = i >> 5;
            As[k * 68 + b] = A[(size_t)b * K + k0 + k];
        }
        for (int i = tid; i < 1024; i += 256) {
            int kk = i >> 5, c2 = i & 31;
            Wt[kk * 32 + c2] = W[(size_t)(k0 + kk) * N + n0 + c2];
        }
        __syncthreads();
#pragma unroll 8
        for (int kk = 0; kk < 32; kk++) {
            float w = Wt[kk * 32 + c];
            float4 a0 = *(const float4*)&As[kk * 68 + rg * 8];
            float4 a1 = *(const float4*)&As[kk * 68 + rg * 8 + 4];
            acc[0] += a0.x * w; acc[1] += a0.y * w;
            acc[2] += a0.z * w; acc[3] += a0.w * w;
            acc[4] += a1.x * w; acc[5] += a1.y * w;
            acc[6] += a1.z * w; acc[7] += a1.w * w;
        }
        __syncthreads();
    }
    float bv = bias ? bias[n] : 0.0f;
#pragma unroll
    for (int r = 0; r < 8; r++) {
        float v = acc[r] + bv;
        if (act == 1) v = tanhf(v);
        C[(size_t)(rg * 8 + r) * N + n] = v;
    }
}

// ------------- fused GRU gate GEMMs: blocks 0-47 xm, 48-95 hm -------------
__global__ __launch_bounds__(256) void k_gates(const float* __restrict__ emb,
                                               const float* __restrict__ Wx,
                                               const float* __restrict__ hid,
                                               const float* __restrict__ Wh,
                                               const float* __restrict__ gb,
                                               float* __restrict__ xm,
                                               float* __restrict__ hm) {
    __shared__ __align__(16) float As[32 * 68];
    __shared__ __align__(16) float Wt[32 * 32];
    const float* A; const float* W; const float* b; float* C; int K; int blk;
    if (blockIdx.x < 48) { A = emb; W = Wx; b = gb;        C = xm; K = 256; blk = blockIdx.x; }
    else                 { A = hid; W = Wh; b = gb + 1536; C = hm; K = 512; blk = blockIdx.x - 48; }
    gemm_tile(As, Wt, A, W, b, C, K, 1536, blk, 0);
}

// ------------- GRU gate combine -> dec_output -------------
__global__ __launch_bounds__(256) void k_comb(const float* __restrict__ hid, float* __restrict__ out) {
    int idx = blockIdx.x * 256 + threadIdx.x;   // 64*512 threads
    int b = idx >> 9, u = idx & 511;
    float xz = g_xm[b * 1536 + u];
    float xr = g_xm[b * 1536 + 512 + u];
    float xh = g_xm[b * 1536 + 1024 + u];
    float hz = g_hm[b * 1536 + u];
    float hr = g_hm[b * 1536 + 512 + u];
    float hh = g_hm[b * 1536 + 1024 + u];
    float z = 1.0f / (1.0f + __expf(-(xz + hz)));
    float r = 1.0f / (1.0f + __expf(-(xr + hr)));
    float hc = tanhf(xh + r * hh);
    float hp = hid[idx];
    out[idx] = z * hp + (1.0f - z) * hc;
}

// ------------- fused q / qw GEMMs: blocks 0-15 q, 16-31 qw -------------
__global__ __launch_bounds__(256) void k_qqw(const float* __restrict__ dec,
                                             const float* __restrict__ Ws,
                                             const float* __restrict__ Ww,
                                             float* __restrict__ q,
                                             float* __restrict__ qw) {
    __shared__ __align__(16) float As[32 * 68];
    __shared__ __align__(16) float Wt[32 * 32];
    const float* W; float* C;
    if (blockIdx.x < 16) { W = Ws; C = q; } else { W = Ww; C = qw; }
    gemm_tile(As, Wt, dec, W, 0, C, 512, 512, blockIdx.x & 15, 0);
}

// ------------- sentence attention + context + p_gen + hidden_t (block per b) -------
__global__ __launch_bounds__(256) void k_att(const float* __restrict__ enc_s,
                                             const float* __restrict__ emb,
                                             const float* __restrict__ wc,
                                             const float* __restrict__ wh,
                                             const float* __restrict__ wi,
                                             const float* __restrict__ wd,
                                             float* __restrict__ out) {
    int b = blockIdx.x;
    __shared__ __align__(16) float qs[512];
    __shared__ __align__(16) float dec_s[512];
    __shared__ float ctx[512];
    __shared__ float sc[32];
    __shared__ float red[8];
    int tid = threadIdx.x, wid = tid >> 5, lane = tid & 31;

    qs[tid] = g_q[b * 512 + tid];
    qs[tid + 256] = g_q[b * 512 + tid + 256];
    dec_s[tid] = out[b * 512 + tid];
    dec_s[tid + 256] = out[b * 512 + tid + 256];
    __syncthreads();

    const float4* qv4 = (const float4*)qs;
    for (int s = wid; s < NS; s += 8) {
        const float4* e = (const float4*)(enc_s + ((size_t)b * NS + s) * 512);
        float sum = 0.0f;
#pragma unroll
        for (int j = 0; j < 4; j++) {
            float4 ev = e[lane + 32 * j];
            float4 qv = qv4[lane + 32 * j];
            sum += ev.x * qv.x + ev.y * qv.y + ev.z * qv.z + ev.w * qv.w;
        }
#pragma unroll
        for (int o = 16; o; o >>= 1) sum += __shfl_xor_sync(0xffffffffu, sum, o);
        if (lane == 0) sc[s] = sum;
    }
    __syncthreads();
    if (wid == 0) {
        float v = sc[lane];
        float m = v;
#pragma unroll
        for (int o = 16; o; o >>= 1) m = fmaxf(m, __shfl_xor_sync(0xffffffffu, m, o));
        float e = __expf(v - m);
        float Z = e;
#pragma unroll
        for (int o = 16; o; o >>= 1) Z += __shfl_xor_sync(0xffffffffu, Z, o);
        float a = e / Z;
        sc[lane] = a;
        g_alpha[b * NS + lane] = a;
    }
    __syncthreads();
    for (int d = tid; d < 512; d += 256) {
        float s = 0.0f;
#pragma unroll 8
        for (int k = 0; k < NS; k++) s += sc[k] * enc_s[((size_t)b * NS + k) * 512 + d];
        ctx[d] = s;
    }
    __syncthreads();
    // p_gen
    {
        float p = ctx[tid] * wc[tid] + ctx[tid + 256] * wc[tid + 256];
        p += dec_s[tid] * wh[tid] + dec_s[tid + 256] * wh[tid + 256];
        p += emb[b * 256 + tid] * wi[tid];
#pragma unroll
        for (int o = 16; o; o >>= 1) p += __shfl_xor_sync(0xffffffffu, p, o);
        if (lane == 0) red[wid] = p;
    }
    __syncthreads();
    if (tid == 0) {
        float t = 0.0f;
        for (int w = 0; w < 8; w++) t += red[w];
        out[PGEN_OFF + b] = 1.0f / (1.0f + __expf(-t));
    }
    // hidden_t = tanh([ctx|dec] @ wd) : thread tid computes column tid
    {
        float acc = 0.0f;
#pragma unroll 8
        for (int k = 0; k < 512; k++) acc += ctx[k] * wd[(size_t)k * 256 + tid];
#pragma unroll 8
        for (int k = 0; k < 512; k++) acc += dec_s[k] * wd[(size_t)(512 + k) * 256 + tid];
        g_ht[b * 256 + tid] = tanhf(acc);
    }
}

// ------------- FC on tensor cores (tf32 mma) + exp + row-sum partials ----------
// grid: 391 blocks x 256 threads; tile 64 batch x 128 vocab
__global__ __launch_bounds__(256) void k_fc(const float* __restrict__ fcW,
                                            const float* __restrict__ fcb,
                                            float* __restrict__ out) {
    __shared__ uint32_t Hs[64 * 36];    // stride 36: conflict-free A frags
    __shared__ uint32_t Wsm[32 * 136];  // stride 136: conflict-free B frags
    __shared__ float bsum[64];

    int tid = threadIdx.x;
    int w = tid >> 5, lane = tid & 31;
    int gid = lane >> 2, tig = lane & 3;
    int mrow = (w & 3) * 16;
    int nloc = (w >> 2) * 64;
    int n0 = blockIdx.x * 128;

    if (tid < 64) bsum[tid] = 0.0f;

    float c[8][4];
#pragma unroll
    for (int t = 0; t < 8; t++)
#pragma unroll
        for (int j = 0; j < 4; j++) c[t][j] = 0.0f;

    for (int ks = 0; ks < 8; ks++) {
        // stage H slice [64][32]
        for (int u = tid; u < 512; u += 256) {
            int row = u >> 3, c4 = (u & 7) * 4;
            float4 v = *(const float4*)(g_ht + row * 256 + ks * 32 + c4);
            Hs[row * 36 + c4 + 0] = f2tf32(v.x);
            Hs[row * 36 + c4 + 1] = f2tf32(v.y);
            Hs[row * 36 + c4 + 2] = f2tf32(v.z);
            Hs[row * 36 + c4 + 3] = f2tf32(v.w);
        }
        // stage W slice [32][128]
        for (int u = tid; u < 1024; u += 256) {
            int k = u >> 5, c4 = (u & 31) * 4;
            int n = n0 + c4;
            const float* src = fcW + (size_t)(ks * 32 + k) * VV + n;
            float4 v = make_float4(0.f, 0.f, 0.f, 0.f);
            if (n + 3 < VV) v = *(const float4*)src;
            else {
                if (n     < VV) v.x = src[0];
                if (n + 1 < VV) v.y = src[1];
                if (n + 2 < VV) v.z = src[2];
            }
            Wsm[k * 136 + c4 + 0] = f2tf32(v.x);
            Wsm[k * 136 + c4 + 1] = f2tf32(v.y);
            Wsm[k * 136 + c4 + 2] = f2tf32(v.z);
            Wsm[k * 136 + c4 + 3] = f2tf32(v.w);
        }
        __syncthreads();
#pragma unroll
        for (int k8 = 0; k8 < 4; k8++) {
            int kb = k8 * 8;
            uint32_t a0 = Hs[(mrow + gid) * 36 + kb + tig];
            uint32_t a1 = Hs[(mrow + gid + 8) * 36 + kb + tig];
            uint32_t a2 = Hs[(mrow + gid) * 36 + kb + tig + 4];
            uint32_t a3 = Hs[(mrow + gid + 8) * 36 + kb + tig + 4];
#pragma unroll
            for (int t = 0; t < 8; t++) {
                uint32_t b0 = Wsm[(kb + tig) * 136 + nloc + t * 8 + gid];
                uint32_t b1 = Wsm[(kb + tig + 4) * 136 + nloc + t * 8 + gid];
                mma_tf32(c[t][0], c[t][1], c[t][2], c[t][3], a0, a1, a2, a3, b0, b1);
            }
        }
        __syncthreads();
    }

    // epilogue: exp(logit + bias), write gen region, partial row sums
    float s0 = 0.0f, s1 = 0.0f;
    int r0 = mrow + gid, r1 = r0 + 8;
#pragma unroll
    for (int t = 0; t < 8; t++) {
        int col = n0 + nloc + t * 8 + 2 * tig;
        if (col < VV) {
            float b0v = fcb[col], b1v = fcb[col + 1];
            float e0 = __expf(c[t][0] + b0v);
            float e1 = __expf(c[t][1] + b1v);
            float e2 = __expf(c[t][2] + b0v);
            float e3 = __expf(c[t][3] + b1v);
            *(float2*)(out + GEN_OFF + (size_t)r0 * EXT + col) = make_float2(e0, e1);
            *(float2*)(out + GEN_OFF + (size_t)r1 * EXT + col) = make_float2(e2, e3);
            s0 += e0 + e1;
            s1 += e2 + e3;
        }
    }
    s0 += __shfl_xor_sync(0xffffffffu, s0, 1);
    s0 += __shfl_xor_sync(0xffffffffu, s0, 2);
    s1 += __shfl_xor_sync(0xffffffffu, s1, 1);
    s1 += __shfl_xor_sync(0xffffffffu, s1, 2);
    if (tig == 0) {
        atomicAdd(&bsum[r0], s0);
        atomicAdd(&bsum[r1], s1);
    }
    __syncthreads();
    if (tid < 64) atomicAdd(&g_rowsum[tid], bsum[tid]);
}

// ------------- normalize gen distribution -------------
__global__ __launch_bounds__(256) void k_norm(float* __restrict__ out) {
    size_t i = (size_t)blockIdx.x * blockDim.x + threadIdx.x;
    size_t stride = (size_t)gridDim.x * blockDim.x;
    size_t total = (size_t)BB * EXT;
    for (size_t t = i; t < total; t += stride) {
        int v = (int)(t % EXT);
        if (v < VV) {
            int b = (int)(t / EXT);
            out[GEN_OFF + t] *= (1.0f / g_rowsum[b]);
        }
    }
}

// ------------- word attention + scatter-add copy distribution -------------
__global__ __launch_bounds__(256) void k_watt(const float* __restrict__ enc_w,
                                              const int* __restrict__ num,
                                              float* __restrict__ out) {
    int b = blockIdx.x >> 5;
    int s = blockIdx.x & 31;
    __shared__ __align__(16) float qs[512];
    __shared__ float sc[64];
    int tid = threadIdx.x, wid = tid >> 5, lane = tid & 31;

    qs[tid] = g_qw[b * 512 + tid];
    qs[tid + 256] = g_qw[b * 512 + tid + 256];
    __syncthreads();

    const float4* qv4 = (const float4*)qs;
    for (int w = wid; w < NW; w += 8) {
        const float4* e = (const float4*)(enc_w + (((size_t)b * NS + s) * NW + w) * 512);
        float sum = 0.0f;
#pragma unroll
        for (int j = 0; j < 4; j++) {
            float4 ev = e[lane + 32 * j];
            float4 qv = qv4[lane + 32 * j];
            sum += ev.x * qv.x + ev.y * qv.y + ev.z * qv.z + ev.w * qv.w;
        }
#pragma unroll
        for (int o = 16; o; o >>= 1) sum += __shfl_xor_sync(0xffffffffu, sum, o);
        if (lane == 0) sc[w] = sum;
    }
    __syncthreads();
    if (wid == 0) {
        float v0 = (lane < NW) ? sc[lane] : -1e30f;
        float v1 = (lane + 32 < NW) ? sc[lane + 32] : -1e30f;
        float m = fmaxf(v0, v1);
#pragma unroll
        for (int o = 16; o; o >>= 1) m = fmaxf(m, __shfl_xor_sync(0xffffffffu, m, o));
        float e0 = (lane < NW) ? __expf(v0 - m) : 0.0f;
        float e1 = (lane + 32 < NW) ? __expf(v1 - m) : 0.0f;
        float Z = e0 + e1;
#pragma unroll
        for (int o = 16; o; o >>= 1) Z += __shfl_xor_sync(0xffffffffu, Z, o);
        float a = g_alpha[b * NS + s] / Z;
        if (lane < NW) sc[lane] = e0 * a;
        if (lane + 32 < NW) sc[lane + 32] = e1 * a;
    }
    __syncthreads();
    if (tid < NW) {
        int idx = num[b * (NS * NW) + s * NW + tid];
        atomicAdd(out + COPY_OFF + (size_t)b * EXT + idx, sc[tid]);
    }
}

// =================== host ===================
extern "C" void kernel_launch(void* const* d_in, const int* in_sizes, int n_in,
                              void* d_out, int out_size) {
    const float *emb = 0, *hid = 0, *enc_s = 0, *enc_w = 0;
    const float *Wx = 0, *Wh = 0, *gb = 0, *Ws = 0, *Ww = 0;
    const float *fcW = 0, *fcb = 0, *wc = 0, *wh = 0, *wd = 0, *wi = 0;
    const int* num = 0;
    int c262 = 0, c512 = 0;
    for (int i = 0; i < n_in; i++) {
        int sz = in_sizes[i];
        const float* p = (const float*)d_in[i];
        switch (sz) {
            case 16384:    emb = p; break;
            case 32768:    hid = p; break;
            case 1048576:  enc_s = p; break;
            case 52428800: enc_w = p; break;
            case 102400:   num = (const int*)d_in[i]; break;
            case 393216:   Wx = p; break;
            case 786432:   Wh = p; break;
            case 3072:     gb = p; break;
            case 12800000: fcW = p; break;
            case 50000:    fcb = p; break;
            case 256:      wi = p; break;
            case 512:      if (c512 == 0) wc = p; else wh = p; c512++; break;
            case 262144:
                if (c262 == 0) Ws = p; else if (c262 == 1) Ww = p; else wd = p;
                c262++; break;
            default: break; // batch_size scalar
        }
    }
    float* out = (float*)d_out;

    float *xm_ptr = 0, *hm_ptr = 0, *q_ptr = 0, *qw_ptr = 0;
    cudaGetSymbolAddress((void**)&xm_ptr, g_xm);
    cudaGetSymbolAddress((void**)&hm_ptr, g_hm);
    cudaGetSymbolAddress((void**)&q_ptr, g_q);
    cudaGetSymbolAddress((void**)&qw_ptr, g_qw);

    k_gates<<<96, 256>>>(emb, Wx, hid, Wh, gb, xm_ptr, hm_ptr);
    k_comb<<<128, 256>>>(hid, out);
    k_qqw<<<32, 256>>>(out, Ws, Ww, q_ptr, qw_ptr);
    k_att<<<64, 256>>>(enc_s, emb, wc, wh, wi, wd, out);
    k_init<<<2048, 256>>>(out);
    k_fc<<<(VV + 127) / 128, 256>>>(fcW, fcb, out);
    k_norm<<<6144, 256>>>(out);
    k_watt<<<BB * NS, 256>>>(enc_w, num, out);
}